// round 1
// baseline (speedup 1.0000x reference)
#include <cuda_runtime.h>
#include <math.h>

// Problem constants
#define BDIM 4
#define CH   128      // dim
#define C3   384      // 3*dim
#define HH   128
#define WW   128
#define HW   (HH*WW)

// Scratch (static device allocations — no cudaMalloc allowed)
__device__ float g_t1 [BDIM * C3 * HW];   // after qkv1 1x1 conv   (96 MB)
__device__ float g_qkv[BDIM * C3 * HW];   // after qkv2 3x3 conv   (96 MB)
__device__ float g_att[BDIM * CH * HW];   // after attention        (32 MB)

// ---------------------------------------------------------------------------
// Kernel 1/4: pointwise conv = GEMM  Y[b,co,h,w] = sum_ci W[co,ci] * X[b,ci,h,w]
// Cin fixed at 128. CTA = one (b,h) row (128 pixels) x 64 couts. 256 threads,
// each computes an 8(co) x 4(w) microtile. X and W staged in smem.
// ---------------------------------------------------------------------------
__global__ __launch_bounds__(256) void gemm1x1_kernel(
    const float* __restrict__ X,   // (B,128,H,W)
    const float* __restrict__ Wt,  // (M,128)
    float* __restrict__ Y,         // (B,M,H,W)
    int M)
{
    extern __shared__ float sm[];
    float* Xs = sm;                 // [128][128]  (ci, w)
    float* Ws = sm + 128 * 128;     // [128][68]   (ci, co) padded

    const int row = blockIdx.x;           // b*H + h
    const int b   = row >> 7;
    const int h   = row & 127;
    const int co0 = blockIdx.y * 64;
    const int tid = threadIdx.x;

    // Stage X row block: 128 ci x 128 w (float4, coalesced)
    {
        const float* xbase = X + ((size_t)b * CH) * HW + (size_t)h * WW;
        for (int i4 = tid; i4 < 128 * 32; i4 += 256) {
            int ci = i4 >> 5;
            int w4 = (i4 & 31) << 2;
            float4 v = *reinterpret_cast<const float4*>(xbase + (size_t)ci * HW + w4);
            *reinterpret_cast<float4*>(Xs + ci * 128 + w4) = v;
        }
    }
    // Stage W tile transposed: Ws[ci][co]
    for (int idx = tid; idx < 64 * 128; idx += 256) {
        int co = idx >> 7;
        int ci = idx & 127;
        Ws[ci * 68 + co] = Wt[(size_t)(co0 + co) * 128 + ci];
    }
    __syncthreads();

    const int tx = tid & 31;     // pixel group: w = tx*4 .. +3
    const int ty = tid >> 5;     // cout group:  co = ty*8 .. +7
    const int w0 = tx * 4;
    const int c0 = ty * 8;

    float acc[8][4];
#pragma unroll
    for (int j = 0; j < 8; j++)
#pragma unroll
        for (int m = 0; m < 4; m++) acc[j][m] = 0.f;

#pragma unroll 2
    for (int ci = 0; ci < 128; ci++) {
        float4 xv = *reinterpret_cast<const float4*>(Xs + ci * 128 + w0);
        const float* wr = Ws + ci * 68 + c0;
        float4 wa = *reinterpret_cast<const float4*>(wr);
        float4 wb = *reinterpret_cast<const float4*>(wr + 4);
        float wv[8] = {wa.x, wa.y, wa.z, wa.w, wb.x, wb.y, wb.z, wb.w};
#pragma unroll
        for (int j = 0; j < 8; j++) {
            acc[j][0] += wv[j] * xv.x;
            acc[j][1] += wv[j] * xv.y;
            acc[j][2] += wv[j] * xv.z;
            acc[j][3] += wv[j] * xv.w;
        }
    }

#pragma unroll
    for (int j = 0; j < 8; j++) {
        float4 o = make_float4(acc[j][0], acc[j][1], acc[j][2], acc[j][3]);
        *reinterpret_cast<float4*>(
            Y + (((size_t)b * M + co0 + c0 + j) * HH + h) * WW + w0) = o;
    }
}

// ---------------------------------------------------------------------------
// Kernel 2: 3x3 SAME conv 384->384 as implicit GEMM.
// CTA = one (b,h) row x 128 couts. K loop over ci chunks of 8 (x9 taps).
// 256 threads as 16x16; each thread: 8(co, contiguous) x 8(w, stride 16).
// ---------------------------------------------------------------------------
#define KC  8
#define XP  132   // padded row width for haloed input (cols 0..129 = w -1..128)

__global__ __launch_bounds__(256) void conv3x3_kernel(const float* __restrict__ Wg)
{
    extern __shared__ float sm[];
    float* Ws = sm;               // [72][128]  (k = ci*9+r*3+s, co)
    float* Xs = sm + 72 * 128;    // [KC][3][XP]

    const int row = blockIdx.x;          // b*H + h
    const int b   = row >> 7;
    const int h   = row & 127;
    const int co0 = blockIdx.y * 128;
    const int tid = threadIdx.x;
    const int tx  = tid & 15;
    const int ty  = tid >> 4;
    const int c0  = ty * 8;

    const int coL   = tid >> 1;          // 0..127
    const int halfk = (tid & 1) * 36;    // 0 or 36

    float acc[8][8];
#pragma unroll
    for (int j = 0; j < 8; j++)
#pragma unroll
        for (int i = 0; i < 8; i++) acc[j][i] = 0.f;

    for (int ci0 = 0; ci0 < C3; ci0 += KC) {
        __syncthreads();  // protect previous iteration's reads

        // Stage weights: Ws[k][co] = W2[co0+co][ci0 + k/9][ (k%9)/3 ][ k%3 ]
        {
            const float* wsrc = Wg + (size_t)(co0 + coL) * (C3 * 9) + ci0 * 9 + halfk;
            float* wdst = Ws + halfk * 128 + coL;
#pragma unroll
            for (int m = 0; m < 36; m++) wdst[m * 128] = wsrc[m];
        }
        // Stage haloed input rows with zero pad: Xs[ci][r][c], c=0..129 -> w = c-1
        for (int idx = tid; idx < KC * 3 * 130; idx += 256) {
            int c  = idx % 130;
            int t  = idx / 130;
            int r  = t % 3;
            int ci = t / 3;
            int wsrc = c - 1;
            int hsrc = h + r - 1;
            float v = 0.f;
            if ((unsigned)wsrc < 128u && (unsigned)hsrc < 128u)
                v = g_t1[(((size_t)b * C3 + ci0 + ci) * HH + hsrc) * WW + wsrc];
            Xs[(ci * 3 + r) * XP + c] = v;
        }
        __syncthreads();

#pragma unroll
        for (int ci = 0; ci < KC; ci++) {
#pragma unroll
            for (int r = 0; r < 3; r++) {
                const float* xrow = Xs + (ci * 3 + r) * XP + tx;
#pragma unroll
                for (int s = 0; s < 3; s++) {
                    const int k = ci * 9 + r * 3 + s;
                    const float* wrow = Ws + k * 128 + c0;
                    float4 wa = *reinterpret_cast<const float4*>(wrow);
                    float4 wb = *reinterpret_cast<const float4*>(wrow + 4);
                    float av[8] = {wa.x, wa.y, wa.z, wa.w, wb.x, wb.y, wb.z, wb.w};
                    float bv[8];
#pragma unroll
                    for (int i = 0; i < 8; i++) bv[i] = xrow[s + 16 * i];
#pragma unroll
                    for (int j = 0; j < 8; j++)
#pragma unroll
                        for (int i = 0; i < 8; i++)
                            acc[j][i] += av[j] * bv[i];
                }
            }
        }
    }

#pragma unroll
    for (int j = 0; j < 8; j++) {
        float* ybase = g_qkv + (((size_t)b * C3 + co0 + c0 + j) * HH + h) * WW + tx;
#pragma unroll
        for (int i = 0; i < 8; i++) ybase[16 * i] = acc[j][i];
    }
}

// ---------------------------------------------------------------------------
// Kernel 3: per-(b,c) spatial attention over width.
//  q,k L2-normalized over w (folded into score scaling), S = q k^T * scale[c],
//  softmax rows, O = S v. One CTA per (b,c) slice; k^T and v in smem.
// ---------------------------------------------------------------------------
__global__ __launch_bounds__(256) void attn_kernel(const float* __restrict__ scale)
{
    extern __shared__ float sm[];
    float* kT   = sm;                    // [128][132] : kT[w*132 + g]
    float* Vs   = sm + 128 * 132;        // [128][132] : Vs[g*132 + w]
    float* qbuf = Vs + 128 * 132;        // [8][132]  per-warp q row
    float* kinv = qbuf + 8 * 132;        // [128]

    const int bc   = blockIdx.x;
    const int b    = bc >> 7;
    const int c    = bc & 127;
    const int tid  = threadIdx.x;
    const int lane = tid & 31;
    const int wp   = tid >> 5;
    const unsigned FULL = 0xffffffffu;

    const float* qg = g_qkv + ((size_t)b * C3 + c) * HW;
    const float* kg = g_qkv + ((size_t)b * C3 + CH + c) * HW;
    const float* vg = g_qkv + ((size_t)b * C3 + 2 * CH + c) * HW;

    for (int idx = tid; idx < HW; idx += 256) {
        int g = idx >> 7;
        int w = idx & 127;
        kT[w * 132 + g] = kg[idx];
        Vs[g * 132 + w] = vg[idx];
    }
    __syncthreads();

    if (tid < 128) {
        float ss = 0.f;
#pragma unroll 4
        for (int w = 0; w < 128; w++) {
            float kv = kT[w * 132 + tid];
            ss += kv * kv;
        }
        kinv[tid] = 1.0f / fmaxf(sqrtf(ss), 1e-12f);
    }
    __syncthreads();

    const float sc = scale[c];
    const int g0 = lane * 4;

    for (int i = wp; i < 128; i += 8) {
        // load + normalize q row i
        float4 q4 = *reinterpret_cast<const float4*>(qg + (size_t)i * WW + lane * 4);
        float ss = q4.x * q4.x + q4.y * q4.y + q4.z * q4.z + q4.w * q4.w;
#pragma unroll
        for (int off = 16; off; off >>= 1) ss += __shfl_xor_sync(FULL, ss, off);
        float qf = sc / fmaxf(sqrtf(ss), 1e-12f);

        *reinterpret_cast<float4*>(qbuf + wp * 132 + lane * 4) = q4;
        __syncwarp();

        // scores: lane owns g = lane*4 .. +3
        float s0 = 0.f, s1 = 0.f, s2 = 0.f, s3 = 0.f;
        const float* kcol = kT + g0;
        const float* qrow = qbuf + wp * 132;
#pragma unroll 4
        for (int w = 0; w < 128; w++) {
            float  qv = qrow[w];
            float4 kv = *reinterpret_cast<const float4*>(kcol + w * 132);
            s0 += qv * kv.x; s1 += qv * kv.y; s2 += qv * kv.z; s3 += qv * kv.w;
        }
        s0 *= qf * kinv[g0 + 0];
        s1 *= qf * kinv[g0 + 1];
        s2 *= qf * kinv[g0 + 2];
        s3 *= qf * kinv[g0 + 3];

        // softmax over 128 values spread across warp
        float mx = fmaxf(fmaxf(s0, s1), fmaxf(s2, s3));
#pragma unroll
        for (int off = 16; off; off >>= 1) mx = fmaxf(mx, __shfl_xor_sync(FULL, mx, off));
        float pr[4];
        pr[0] = __expf(s0 - mx); pr[1] = __expf(s1 - mx);
        pr[2] = __expf(s2 - mx); pr[3] = __expf(s3 - mx);
        float psum = pr[0] + pr[1] + pr[2] + pr[3];
#pragma unroll
        for (int off = 16; off; off >>= 1) psum += __shfl_xor_sync(FULL, psum, off);
        float inv = 1.0f / psum;

        // O row: lane owns w = lane*4 .. +3
        float o0 = 0.f, o1 = 0.f, o2 = 0.f, o3 = 0.f;
#pragma unroll
        for (int jj = 0; jj < 4; jj++) {
#pragma unroll
            for (int l = 0; l < 32; l++) {
                float pv = __shfl_sync(FULL, pr[jj], l);
                int g = l * 4 + jj;
                float4 vv = *reinterpret_cast<const float4*>(Vs + g * 132 + lane * 4);
                o0 += pv * vv.x; o1 += pv * vv.y; o2 += pv * vv.z; o3 += pv * vv.w;
            }
        }
        float4 orow = make_float4(o0 * inv, o1 * inv, o2 * inv, o3 * inv);
        *reinterpret_cast<float4*>(
            g_att + (((size_t)b * CH + c) * HH + i) * WW + lane * 4) = orow;
        __syncwarp();
    }
}

// ---------------------------------------------------------------------------
// Launch
// ---------------------------------------------------------------------------
extern "C" void kernel_launch(void* const* d_in, const int* in_sizes, int n_in,
                              void* d_out, int out_size)
{
    (void)in_sizes; (void)n_in; (void)out_size;
    const float* x     = (const float*)d_in[0];
    const float* w1    = (const float*)d_in[1];  // (384,128,1,1)
    const float* w2    = (const float*)d_in[2];  // (384,384,3,3)
    const float* wproj = (const float*)d_in[3];  // (128,128,1,1)
    const float* scale = (const float*)d_in[4];  // (128,1,1)
    float* out = (float*)d_out;

    void *p_t1 = nullptr, *p_att = nullptr;
    cudaGetSymbolAddress(&p_t1, g_t1);
    cudaGetSymbolAddress(&p_att, g_att);

    const int SMEM_GEMM = (128 * 128 + 128 * 68) * 4;             // 100,352 B
    const int SMEM_CONV = (72 * 128 + KC * 3 * XP) * 4;           //  49,536 B
    const int SMEM_ATTN = (128 * 132 * 2 + 8 * 132 + 128) * 4;    // 139,904 B

    cudaFuncSetAttribute(gemm1x1_kernel, cudaFuncAttributeMaxDynamicSharedMemorySize, SMEM_GEMM);
    cudaFuncSetAttribute(conv3x3_kernel, cudaFuncAttributeMaxDynamicSharedMemorySize, SMEM_CONV);
    cudaFuncSetAttribute(attn_kernel,    cudaFuncAttributeMaxDynamicSharedMemorySize, SMEM_ATTN);

    // 1) qkv 1x1: x(128ch) -> g_t1(384ch)
    gemm1x1_kernel<<<dim3(BDIM * HH, C3 / 64), 256, SMEM_GEMM>>>(
        x, w1, (float*)p_t1, C3);

    // 2) qkv 3x3: g_t1 -> g_qkv
    conv3x3_kernel<<<dim3(BDIM * HH, C3 / 128), 256, SMEM_CONV>>>(w2);

    // 3) attention: g_qkv -> g_att
    attn_kernel<<<BDIM * CH, 256, SMEM_ATTN>>>(scale);

    // 4) proj 1x1: g_att(128ch) -> out(128ch)
    gemm1x1_kernel<<<dim3(BDIM * HH, CH / 64), 256, SMEM_GEMM>>>(
        (const float*)p_att, wproj, out, CH);
}